// round 1
// baseline (speedup 1.0000x reference)
#include <cuda_runtime.h>

#define NPTS 6912
#define CF 16
#define BB 2
#define TILE 128
#define NT (NPTS / TILE)   /* 54 */
#define EPSF 1e-8f
/* exp(-sq/0.1) = 2^(NEG_SCALE * sq), NEG_SCALE = -10*log2(e) */
#define NEG_SCALE (-14.426950408889634f)
#define POS2SCALE (28.853900817779268f)

typedef unsigned long long u64;

/* ------------------------- device scratch (no allocs allowed) ----------- */
__device__ float  g_f1n[BB][CF][NPTS];
__device__ float  g_f2n[BB][CF][NPTS];
__device__ float  g_x1 [BB][3][NPTS];
__device__ float  g_x2 [BB][3][NPTS];
__device__ float  g_x2t[BB][3][NPTS];
__device__ float  g_as [BB][NPTS];   /* NEG_SCALE * ||xyz1||^2  */
__device__ float  g_bts[BB][NPTS];   /* NEG_SCALE * ||xyz2t||^2 */
__device__ float  g_bns[BB][NPTS];   /* NEG_SCALE * ||xyz2||^2  */
__device__ float  g_scal[BB][3];     /* 0: sum n1*m1+n2*m2, 1: sum m1, 2: sum m2 */
__device__ double g_S[BB];

/* ------------------------- packed f32x2 helpers ------------------------- */
__device__ __forceinline__ u64 pack2(float lo, float hi) {
    u64 r; asm("mov.b64 %0, {%1, %2};" : "=l"(r) : "f"(lo), "f"(hi)); return r;
}
__device__ __forceinline__ float2 unpk(u64 v) {
    float2 r; asm("mov.b64 {%0, %1}, %2;" : "=f"(r.x), "=f"(r.y) : "l"(v)); return r;
}
__device__ __forceinline__ void fma2(u64 &d, u64 a, u64 b) {
    asm("fma.rn.f32x2 %0, %1, %2, %0;" : "+l"(d) : "l"(a), "l"(b));
}
__device__ __forceinline__ u64 mul2(u64 a, u64 b) {
    u64 r; asm("mul.rn.f32x2 %0, %1, %2;" : "=l"(r) : "l"(a), "l"(b)); return r;
}
__device__ __forceinline__ u64 add2(u64 a, u64 b) {
    u64 r; asm("add.rn.f32x2 %0, %1, %2;" : "=l"(r) : "l"(a), "l"(b)); return r;
}
__device__ __forceinline__ float fexp2(float x) {
    float r; asm("ex2.approx.f32 %0, %1;" : "=f"(r) : "f"(x)); return r;
}

/* ------------------------- init: zero accumulators ---------------------- */
__global__ void init_kernel() {
    int t = threadIdx.x;
    if (t < BB) g_S[t] = 0.0;
    if (t < BB * 3) ((float*)g_scal)[t] = 0.f;
}

/* ------------------------- prep: per-point quantities ------------------- */
__global__ void prep_kernel(const float* __restrict__ f1, const float* __restrict__ f2,
                            const float* __restrict__ dp1, const float* __restrict__ dp2,
                            const float* __restrict__ pose, const float* __restrict__ yz1) {
    const int b = blockIdx.y;
    const int i = blockIdx.x * blockDim.x + threadIdx.x;
    float fns = 0.f, m1c = 0.f, m2c = 0.f;
    if (i < NPTS) {
        float d1 = dp1[b * NPTS + i], d2 = dp2[b * NPTS + i];
        float m1 = (d1 > 0.f) ? 1.f : 0.f;
        float m2 = (d2 > 0.f) ? 1.f : 0.f;
        float v1[CF], v2[CF];
        float s1 = 0.f, s2 = 0.f;
#pragma unroll
        for (int c = 0; c < CF; c++) {
            v1[c] = f1[((size_t)b * CF + c) * NPTS + i];
            v2[c] = f2[((size_t)b * CF + c) * NPTS + i];
            s1 = fmaf(v1[c], v1[c], s1);
            s2 = fmaf(v2[c], v2[c], s2);
        }
        float n1 = sqrtf(s1), n2 = sqrtf(s2);
        float iv1 = m1 / (n1 + EPSF), iv2 = m2 / (n2 + EPSF);
#pragma unroll
        for (int c = 0; c < CF; c++) {
            g_f1n[b][c][i] = v1[c] * iv1;
            g_f2n[b][c][i] = v2[c] * iv2;
        }
        float y0 = yz1[i], y1 = yz1[NPTS + i], y2 = yz1[2 * NPTS + i];
        float ax = y0 * d1, ay = y1 * d1, az = y2 * d1;
        g_x1[b][0][i] = ax; g_x1[b][1][i] = ay; g_x1[b][2][i] = az;
        g_as[b][i] = NEG_SCALE * (ax * ax + ay * ay + az * az);
        float bx = y0 * d2, by = y1 * d2, bz = y2 * d2;
        g_x2[b][0][i] = bx; g_x2[b][1][i] = by; g_x2[b][2][i] = bz;
        g_bns[b][i] = NEG_SCALE * (bx * bx + by * by + bz * bz);
        const float* P = pose + b * 16;
        float tx = P[0] * bx + P[1] * by + P[2]  * bz + P[3];
        float ty = P[4] * bx + P[5] * by + P[6]  * bz + P[7];
        float tz = P[8] * bx + P[9] * by + P[10] * bz + P[11];
        g_x2t[b][0][i] = tx; g_x2t[b][1][i] = ty; g_x2t[b][2][i] = tz;
        g_bts[b][i] = NEG_SCALE * (tx * tx + ty * ty + tz * tz);
        fns = n1 * m1 + n2 * m2; m1c = m1; m2c = m2;
    }
    /* block reduce the three scalars, one atomic per block */
#pragma unroll
    for (int o = 16; o; o >>= 1) {
        fns += __shfl_down_sync(0xffffffffu, fns, o);
        m1c += __shfl_down_sync(0xffffffffu, m1c, o);
        m2c += __shfl_down_sync(0xffffffffu, m2c, o);
    }
    __shared__ float rf[8], r1[8], r2[8];
    int w = threadIdx.x >> 5, l = threadIdx.x & 31;
    if (l == 0) { rf[w] = fns; r1[w] = m1c; r2[w] = m2c; }
    __syncthreads();
    if (threadIdx.x == 0) {
        float a = 0.f, c1 = 0.f, c2 = 0.f;
#pragma unroll
        for (int k = 0; k < 8; k++) { a += rf[k]; c1 += r1[k]; c2 += r2[k]; }
        atomicAdd(&g_scal[b][0], a);
        atomicAdd(&g_scal[b][1], c1);
        atomicAdd(&g_scal[b][2], c2);
    }
}

/* ------------------------- main: 128x128 pair tiles --------------------- */
__global__ __launch_bounds__(512, 1) void pair_kernel() {
    const int b   = blockIdx.z;
    const int i0  = blockIdx.y * TILE;
    const int j0b = blockIdx.x * TILE;

    __shared__ float sA[CF][TILE];
    __shared__ float sB[CF][TILE];
    __shared__ float sX1[3][TILE];
    __shared__ float sXT[3][TILE];
    __shared__ float sXN[3][TILE];
    __shared__ float sa[TILE], sbt[TILE], sbn[TILE];

    const int tid = threadIdx.x;

    /* cooperative tile loads (all float4, rows are 16B aligned) */
    {
        float4* dA = (float4*)sA;
        float4* dB = (float4*)sB;
        int c = tid >> 5, q = tid & 31;           /* tid < 512 == CF*TILE/4 */
        dA[tid] = *(const float4*)&g_f1n[b][c][i0 + q * 4];
        dB[tid] = *(const float4*)&g_f2n[b][c][j0b + q * 4];
        if (tid < 3 * TILE / 4) {                 /* 96 */
            int cc = tid >> 5, qq = tid & 31;
            ((float4*)sX1)[tid] = *(const float4*)&g_x1 [b][cc][i0  + qq * 4];
            ((float4*)sXT)[tid] = *(const float4*)&g_x2t[b][cc][j0b + qq * 4];
            ((float4*)sXN)[tid] = *(const float4*)&g_x2 [b][cc][j0b + qq * 4];
        }
        if (tid < TILE / 4) {                     /* 32 */
            ((float4*)sa )[tid] = *(const float4*)&g_as [b][i0  + tid * 4];
            ((float4*)sbt)[tid] = *(const float4*)&g_bts[b][j0b + tid * 4];
            ((float4*)sbn)[tid] = *(const float4*)&g_bns[b][j0b + tid * 4];
        }
    }
    __syncthreads();

    const int ty = tid >> 5;   /* 0..15: i block of 8 */
    const int tx = tid & 31;   /* 0..31: j block of 4 */
    const int iL = ty * 8;
    const int jL = tx * 4;

    /* ---- gramian: 8i x 4j per thread, packed f32x2 over j-pairs ---- */
    u64 acc[8][2];
#pragma unroll
    for (int ii = 0; ii < 8; ii++) { acc[ii][0] = 0ull; acc[ii][1] = 0ull; }

    const float4* A4 = (const float4*)sA;
    const float4* B4 = (const float4*)sB;
#pragma unroll
    for (int c = 0; c < CF; c++) {
        float4 a0 = A4[c * 32 + ty * 2];
        float4 a1 = A4[c * 32 + ty * 2 + 1];
        float4 bv = B4[c * 32 + tx];
        u64 bp0 = pack2(bv.x, bv.y);
        u64 bp1 = pack2(bv.z, bv.w);
        float av[8] = {a0.x, a0.y, a0.z, a0.w, a1.x, a1.y, a1.z, a1.w};
#pragma unroll
        for (int ii = 0; ii < 8; ii++) {
            u64 ap = pack2(av[ii], av[ii]);
            fma2(acc[ii][0], ap, bp0);
            fma2(acc[ii][1], ap, bp1);
        }
    }

    /* ---- RBF weight phase: packed distance dots, MUFU exp ---- */
    u64 xt2[3][2], xn2[3][2], bt2[2], bn2[2];
#pragma unroll
    for (int cmp = 0; cmp < 3; cmp++) {
        xt2[cmp][0] = *(const u64*)&sXT[cmp][jL];
        xt2[cmp][1] = *(const u64*)&sXT[cmp][jL + 2];
        xn2[cmp][0] = *(const u64*)&sXN[cmp][jL];
        xn2[cmp][1] = *(const u64*)&sXN[cmp][jL + 2];
    }
    bt2[0] = *(const u64*)&sbt[jL]; bt2[1] = *(const u64*)&sbt[jL + 2];
    bn2[0] = *(const u64*)&sbn[jL]; bn2[1] = *(const u64*)&sbn[jL + 2];

    const u64 K2 = pack2(POS2SCALE, POS2SCALE);

    float part = 0.f;
#pragma unroll
    for (int ii = 0; ii < 8; ii++) {
        const int i = iL + ii;
        float x0 = sX1[0][i], x1v = sX1[1][i], x2v = sX1[2][i], asv = sa[i];
        u64 px = pack2(x0, x0);
        u64 py = pack2(x1v, x1v);
        u64 pz = pack2(x2v, x2v);
        u64 pa = pack2(asv, asv);
#pragma unroll
        for (int jp = 0; jp < 2; jp++) {
            u64 dt = mul2(px, xt2[0][jp]);
            fma2(dt, py, xt2[1][jp]);
            fma2(dt, pz, xt2[2][jp]);
            u64 dn = mul2(px, xn2[0][jp]);
            fma2(dn, py, xn2[1][jp]);
            fma2(dn, pz, xn2[2][jp]);
            /* scaled -sq/d: NEG*(a+b) + 2*POS*dot ; clamp sq>=0 -> min(.,0) */
            u64 st = add2(pa, bt2[jp]); fma2(st, K2, dt);
            u64 sn = add2(pa, bn2[jp]); fma2(sn, K2, dn);
            float2 stf = unpk(st), snf = unpk(sn), g = unpk(acc[ii][jp]);
            float w0 = fexp2(fminf(stf.x, 0.f)) - fexp2(fminf(snf.x, 0.f));
            float w1 = fexp2(fminf(stf.y, 0.f)) - fexp2(fminf(snf.y, 0.f));
            part = fmaf(w0, g.x, part);
            part = fmaf(w1, g.y, part);
        }
    }

    /* ---- block reduce -> one double atomic ---- */
#pragma unroll
    for (int o = 16; o; o >>= 1) part += __shfl_down_sync(0xffffffffu, part, o);
    __shared__ float warpsum[16];
    if ((tid & 31) == 0) warpsum[tid >> 5] = part;
    __syncthreads();
    if (tid == 0) {
        float s = 0.f;
#pragma unroll
        for (int w = 0; w < 16; w++) s += warpsum[w];
        atomicAdd(&g_S[b], (double)s);
    }
}

/* ------------------------- finalize ------------------------------------ */
__global__ void fin_kernel(float* out) {
    double tot = 0.0;
#pragma unroll
    for (int b = 0; b < BB; b++)
        tot += g_S[b] / ((double)g_scal[b][1] * (double)g_scal[b][2]);
    float fl = (float)(-tot);
    out[0] = fl;                                      /* sum final_loss  */
    out[1] = fl;                                      /* sum inner_neg   */
    out[2] = (g_scal[0][0] + g_scal[1][0]) * 100.f;   /* sum fea_norm    */
}

/* ------------------------- launch --------------------------------------- */
extern "C" void kernel_launch(void* const* d_in, const int* in_sizes, int n_in,
                              void* d_out, int out_size) {
    const float* f1   = (const float*)d_in[0];
    const float* f2   = (const float*)d_in[1];
    const float* dp1  = (const float*)d_in[2];
    const float* dp2  = (const float*)d_in[3];
    const float* pose = (const float*)d_in[4];
    /* d_in[5], d_in[6] (img1, img2) unused by the loss */
    const float* yz1  = (const float*)d_in[7];
    float* out = (float*)d_out;

    init_kernel<<<1, 32>>>();
    prep_kernel<<<dim3(NPTS / 256, BB), 256>>>(f1, f2, dp1, dp2, pose, yz1);
    pair_kernel<<<dim3(NT, NT, BB), 512>>>();
    fin_kernel<<<1, 1>>>(out);
}